// round 1
// baseline (speedup 1.0000x reference)
#include <cuda_runtime.h>

#define B_  2
#define H_  16
#define T_  2048
#define S_  2048
#define D_  1024
#define HD_ 64

// Scratch (allocation-free rule: device globals)
__device__ float g_Q[B_*H_*T_*HD_];   // 16 MB, head-split, pre-scaled by 1/sqrt(HD)
__device__ float g_K[B_*H_*S_*HD_];
__device__ float g_V[B_*H_*S_*HD_];
__device__ float g_C[B_*T_*D_];       // attention context, [B,T,D]

// ---------------------------------------------------------------------------
// Generic GEMM:  out = alpha * (A[M,K] @ W[N,K]^T + bias[N])
// 64x64 block tile, 256 threads, 4x4 per-thread microtile, K-tile = 16.
// split=1 writes head-split layout [B,H,len,HD]; split=0 writes [M,N] plain.
// ---------------------------------------------------------------------------
__global__ __launch_bounds__(256) void gemm_bias_kernel(
    const float* __restrict__ A, const float* __restrict__ W,
    const float* __restrict__ bias, float* __restrict__ out,
    int K, int split, float alpha)
{
    __shared__ float Ast[16][68];  // [k][m], padded
    __shared__ float Bst[16][68];  // [k][n], padded

    const int tid = threadIdx.x;
    const int tx = tid & 15, ty = tid >> 4;
    const int m0 = blockIdx.y * 64, n0 = blockIdx.x * 64;
    const int lr = tid >> 2;          // 0..63
    const int lk = (tid & 3) << 2;    // 0,4,8,12

    const float* Ap = A + (size_t)(m0 + lr) * K + lk;
    const float* Wp = W + (size_t)(n0 + lr) * K + lk;

    float acc[4][4] = {};

    for (int kt = 0; kt < K; kt += 16) {
        float4 av = *(const float4*)(Ap + kt);
        float4 wv = *(const float4*)(Wp + kt);
        __syncthreads();
        Ast[lk+0][lr]=av.x; Ast[lk+1][lr]=av.y; Ast[lk+2][lr]=av.z; Ast[lk+3][lr]=av.w;
        Bst[lk+0][lr]=wv.x; Bst[lk+1][lr]=wv.y; Bst[lk+2][lr]=wv.z; Bst[lk+3][lr]=wv.w;
        __syncthreads();
        #pragma unroll
        for (int kk = 0; kk < 16; kk++) {
            float4 a4 = *(const float4*)&Ast[kk][ty << 2];
            float4 b4 = *(const float4*)&Bst[kk][tx << 2];
            const float ar[4] = {a4.x, a4.y, a4.z, a4.w};
            const float br[4] = {b4.x, b4.y, b4.z, b4.w};
            #pragma unroll
            for (int i = 0; i < 4; i++)
                #pragma unroll
                for (int j = 0; j < 4; j++)
                    acc[i][j] += ar[i] * br[j];
        }
    }

    #pragma unroll
    for (int i = 0; i < 4; i++) {
        const int m = m0 + (ty << 2) + i;
        #pragma unroll
        for (int j = 0; j < 4; j++) {
            const int n = n0 + (tx << 2) + j;
            const float v = alpha * (acc[i][j] + bias[n]);
            if (split) {
                const int bb = m >> 11, t = m & (T_ - 1);
                const int h  = n >> 6,  d = n & (HD_ - 1);
                out[((size_t)(bb * H_ + h) * T_ + t) * HD_ + d] = v;
            } else {
                out[(size_t)m * D_ + n] = v;
            }
        }
    }
}

// ---------------------------------------------------------------------------
// Flash attention: one block = (b, h, 64 T-rows). Streams S in 64-wide tiles.
// Q pre-scaled. scores = Q·K^T + bias (+ -1e30 where padding-masked),
// online softmax, O += P·V. 256 threads, 4x4 microtiles throughout.
// ---------------------------------------------------------------------------
__global__ __launch_bounds__(256) void attn_kernel(
    const float* __restrict__ Q, const float* __restrict__ K,
    const float* __restrict__ V, const float* __restrict__ bias,
    const unsigned char* __restrict__ mask, float* __restrict__ Ctx)
{
    extern __shared__ float sm[];
    float* Qt   = sm;              // [64][68], d-major (transposed)
    float* Kt   = Qt + 64 * 68;    // [64][68], d-major (transposed)
    float* Vs   = Kt + 64 * 68;    // [64][68], s-major
    float* Pt   = Vs + 64 * 68;    // [64][68], s-major (P transposed: [s][t])
    float* madd = Pt + 64 * 68;    // [64] additive mask

    const int tid = threadIdx.x;
    const int tx = tid & 15, ty = tid >> 4;
    const int t0 = blockIdx.x * 64;
    const int h  = blockIdx.y;
    const int b  = blockIdx.z;
    const int bh = b * H_ + h;

    const float* Qbase = Q + ((size_t)bh * T_ + t0) * HD_;
    const float* Kbase = K + (size_t)bh * S_ * HD_;
    const float* Vbase = V + (size_t)bh * S_ * HD_;
    const float* Bbase = bias + ((size_t)bh * T_ + t0) * (size_t)S_;

    // Load Q tile, transposed into Qt[d][t]
    {
        const int r  = tid >> 4;          // 0..15
        const int d0 = (tid & 15) << 2;   // 0..60
        #pragma unroll
        for (int rep = 0; rep < 4; rep++) {
            const int row = rep * 16 + r;
            float4 q4 = *(const float4*)(Qbase + row * HD_ + d0);
            Qt[(d0+0)*68 + row] = q4.x; Qt[(d0+1)*68 + row] = q4.y;
            Qt[(d0+2)*68 + row] = q4.z; Qt[(d0+3)*68 + row] = q4.w;
        }
    }

    float oa[4][4] = {};
    float mrun[4] = {-1e30f, -1e30f, -1e30f, -1e30f};
    float lrun[4] = {};

    for (int s0 = 0; s0 < S_; s0 += 64) {
        __syncthreads();  // protect Kt/Vs/Pt from previous iteration's readers
        // Load K (transposed), V (direct), padding mask
        {
            const int r  = tid >> 4;
            const int d0 = (tid & 15) << 2;
            #pragma unroll
            for (int rep = 0; rep < 4; rep++) {
                const int row = rep * 16 + r;
                float4 k4 = *(const float4*)(Kbase + (size_t)(s0 + row) * HD_ + d0);
                Kt[(d0+0)*68 + row] = k4.x; Kt[(d0+1)*68 + row] = k4.y;
                Kt[(d0+2)*68 + row] = k4.z; Kt[(d0+3)*68 + row] = k4.w;
                float4 v4 = *(const float4*)(Vbase + (size_t)(s0 + row) * HD_ + d0);
                *(float4*)&Vs[row * 68 + d0] = v4;
            }
            if (tid < 64) madd[tid] = mask[b * S_ + s0 + tid] ? -1e30f : 0.0f;
        }
        __syncthreads();

        // Scores: sc[i][j] = sum_d Q[t][d] * K[s][d]
        float sc[4][4] = {};
        #pragma unroll 8
        for (int d = 0; d < 64; d++) {
            float4 a4 = *(const float4*)&Qt[d * 68 + (ty << 2)];
            float4 b4 = *(const float4*)&Kt[d * 68 + (tx << 2)];
            const float ar[4] = {a4.x, a4.y, a4.z, a4.w};
            const float br[4] = {b4.x, b4.y, b4.z, b4.w};
            #pragma unroll
            for (int i = 0; i < 4; i++)
                #pragma unroll
                for (int j = 0; j < 4; j++)
                    sc[i][j] += ar[i] * br[j];
        }

        // + bias + padding mask
        const float mj0 = madd[(tx<<2)+0], mj1 = madd[(tx<<2)+1];
        const float mj2 = madd[(tx<<2)+2], mj3 = madd[(tx<<2)+3];
        #pragma unroll
        for (int i = 0; i < 4; i++) {
            float4 bi = *(const float4*)(Bbase + (size_t)((ty<<2)+i) * S_ + s0 + (tx<<2));
            sc[i][0] += bi.x + mj0; sc[i][1] += bi.y + mj1;
            sc[i][2] += bi.z + mj2; sc[i][3] += bi.w + mj3;
        }

        // Online softmax (row reductions across the 16 tx lanes of a half-warp)
        #pragma unroll
        for (int i = 0; i < 4; i++) {
            float tm = fmaxf(fmaxf(sc[i][0], sc[i][1]), fmaxf(sc[i][2], sc[i][3]));
            #pragma unroll
            for (int off = 8; off >= 1; off >>= 1)
                tm = fmaxf(tm, __shfl_xor_sync(0xffffffffu, tm, off));
            const float mnew = fmaxf(mrun[i], tm);
            const float corr = __expf(mrun[i] - mnew);
            mrun[i] = mnew;
            float ps = 0.0f;
            #pragma unroll
            for (int j = 0; j < 4; j++) {
                const float p = __expf(sc[i][j] - mnew);
                Pt[((tx<<2)+j) * 68 + (ty<<2) + i] = p;  // P transposed [s][t]
                ps += p;
            }
            #pragma unroll
            for (int off = 8; off >= 1; off >>= 1)
                ps += __shfl_xor_sync(0xffffffffu, ps, off);
            lrun[i] = lrun[i] * corr + ps;
            oa[i][0] *= corr; oa[i][1] *= corr; oa[i][2] *= corr; oa[i][3] *= corr;
        }
        __syncthreads();

        // O += P @ V
        #pragma unroll 8
        for (int s = 0; s < 64; s++) {
            float4 p4 = *(const float4*)&Pt[s * 68 + (ty << 2)];
            float4 v4 = *(const float4*)&Vs[s * 68 + (tx << 2)];
            const float pr[4] = {p4.x, p4.y, p4.z, p4.w};
            const float vr[4] = {v4.x, v4.y, v4.z, v4.w};
            #pragma unroll
            for (int i = 0; i < 4; i++)
                #pragma unroll
                for (int j = 0; j < 4; j++)
                    oa[i][j] += pr[i] * vr[j];
        }
    }

    // Normalize and write context in [B,T,D] layout for the output projection
    #pragma unroll
    for (int i = 0; i < 4; i++) {
        const float inv = 1.0f / lrun[i];
        float4 o4;
        o4.x = oa[i][0]*inv; o4.y = oa[i][1]*inv; o4.z = oa[i][2]*inv; o4.w = oa[i][3]*inv;
        const int t = t0 + (ty << 2) + i;
        *(float4*)&Ctx[((size_t)b * T_ + t) * D_ + h * HD_ + (tx << 2)] = o4;
    }
}

// ---------------------------------------------------------------------------
extern "C" void kernel_launch(void* const* d_in, const int* in_sizes, int n_in,
                              void* d_out, int out_size)
{
    (void)in_sizes; (void)n_in; (void)out_size;
    const float* query = (const float*)d_in[0];
    const float* key   = (const float*)d_in[1];
    const float* value = (const float*)d_in[2];
    const float* bias  = (const float*)d_in[3];
    const unsigned char* mask = (const unsigned char*)d_in[4];
    const float* Wq = (const float*)d_in[5];
    const float* bq = (const float*)d_in[6];
    const float* Wk = (const float*)d_in[7];
    const float* bk = (const float*)d_in[8];
    const float* Wv = (const float*)d_in[9];
    const float* bv = (const float*)d_in[10];
    const float* Wo = (const float*)d_in[11];
    const float* bo = (const float*)d_in[12];

    float *qp, *kp, *vp, *cp;
    cudaGetSymbolAddress((void**)&qp, g_Q);
    cudaGetSymbolAddress((void**)&kp, g_K);
    cudaGetSymbolAddress((void**)&vp, g_V);
    cudaGetSymbolAddress((void**)&cp, g_C);

    const dim3 gemmGrid(D_ / 64, (B_ * T_) / 64);  // (16, 64)
    const float qscale = 0.125f;  // HD^-0.5 folded into Q projection (incl. bias)

    gemm_bias_kernel<<<gemmGrid, 256>>>(query, Wq, bq, qp, D_, 1, qscale);
    gemm_bias_kernel<<<gemmGrid, 256>>>(key,   Wk, bk, kp, D_, 1, 1.0f);
    gemm_bias_kernel<<<gemmGrid, 256>>>(value, Wv, bv, vp, D_, 1, 1.0f);

    const int ATTN_SMEM = (4 * 64 * 68 + 64) * (int)sizeof(float);  // 69,888 B
    cudaFuncSetAttribute(attn_kernel, cudaFuncAttributeMaxDynamicSharedMemorySize,
                         ATTN_SMEM);
    attn_kernel<<<dim3(T_ / 64, H_, B_), 256, ATTN_SMEM>>>(qp, kp, vp, bias, mask, cp);

    gemm_bias_kernel<<<gemmGrid, 256>>>(cp, Wo, bo, (float*)d_out, D_, 0, 1.0f);
}

// round 3
// speedup vs baseline: 1.9116x; 1.9116x over previous
#include <cuda_runtime.h>
#include <cstdint>

#define B_  2
#define H_  16
#define T_  2048
#define S_  2048
#define D_  1024
#define HD_ 64

// Scratch (allocation-free rule: device globals)
__device__ float g_Q[B_*H_*T_*HD_];   // head-split, pre-scaled by 1/sqrt(HD)
__device__ float g_K[B_*H_*S_*HD_];
__device__ float g_V[B_*H_*S_*HD_];
__device__ float g_C[B_*T_*D_];       // attention context, [B,T,D]

// ---------------------------------------------------------------------------
// tf32 helpers (baseline sm_80+ PTX — works at compute_103 virtual arch)
// ---------------------------------------------------------------------------
__device__ __forceinline__ uint32_t f2tf32(float f) {
    uint32_t u;
    asm("cvt.rna.tf32.f32 %0, %1;" : "=r"(u) : "f"(f));
    return u;
}

// D += A(16x8,row) * B(8x8,col); C/D in place.
__device__ __forceinline__ void mma8(float* d, const uint32_t* a, const uint32_t* b) {
    asm volatile("mma.sync.aligned.m16n8k8.row.col.f32.tf32.tf32.f32 "
                 "{%0,%1,%2,%3}, {%4,%5,%6,%7}, {%8,%9}, {%0,%1,%2,%3};"
                 : "+f"(d[0]), "+f"(d[1]), "+f"(d[2]), "+f"(d[3])
                 : "r"(a[0]), "r"(a[1]), "r"(a[2]), "r"(a[3]),
                   "r"(b[0]), "r"(b[1]));
}

// ---------------------------------------------------------------------------
// tf32 tensor-core GEMM: out = alpha * (A[M,1024] @ W[N,1024]^T + bias[N])
// CTA tile 128x128, 256 threads (8 warps of 64x32), K-tile 32, reg prefetch.
// Smem k-major, stride 136 floats -> conflict-free fragment LDS.
// ---------------------------------------------------------------------------
#define ASTRIDE 136

__global__ __launch_bounds__(256) void gemm_tc(
    const float* __restrict__ A, const float* __restrict__ W,
    const float* __restrict__ bias, float* __restrict__ out,
    int split, float alpha)
{
    __shared__ uint32_t As[32 * ASTRIDE];
    __shared__ uint32_t Ws[32 * ASTRIDE];

    const int tid  = threadIdx.x;
    const int wid  = tid >> 5, lane = tid & 31;
    const int gid  = lane >> 2, tig = lane & 3;
    const int m0   = blockIdx.y * 128, n0 = blockIdx.x * 128;
    const int wm   = (wid & 1) * 64, wn = (wid >> 1) * 32;

    const int lrow = tid & 127;         // 0..127 (m for A, n for W)
    const int lks  = (tid >> 7) * 16;   // 0 or 16

    const float* Ap = A + (size_t)(m0 + lrow) * 1024 + lks;
    const float* Wp = W + (size_t)(n0 + lrow) * 1024 + lks;

    float4 pa[4], pw[4];
    #pragma unroll
    for (int q = 0; q < 4; q++) {
        pa[q] = *(const float4*)(Ap + q * 4);
        pw[q] = *(const float4*)(Wp + q * 4);
    }

    float acc[4][4][4] = {};  // [mt][nt][frag]

    for (int kt = 0; kt < 32; kt++) {
        // store prefetched tile (tf32-converted)
        #pragma unroll
        for (int q = 0; q < 4; q++) {
            const int k = lks + q * 4;
            const float* va = (const float*)&pa[q];
            const float* vw = (const float*)&pw[q];
            #pragma unroll
            for (int j = 0; j < 4; j++) {
                As[(k + j) * ASTRIDE + lrow] = f2tf32(va[j]);
                Ws[(k + j) * ASTRIDE + lrow] = f2tf32(vw[j]);
            }
        }
        __syncthreads();

        if (kt < 31) {
            #pragma unroll
            for (int q = 0; q < 4; q++) {
                pa[q] = *(const float4*)(Ap + (kt + 1) * 32 + q * 4);
                pw[q] = *(const float4*)(Wp + (kt + 1) * 32 + q * 4);
            }
        }

        #pragma unroll
        for (int kb = 0; kb < 32; kb += 8) {
            uint32_t af[4][4], bf[4][2];
            #pragma unroll
            for (int mt = 0; mt < 4; mt++) {
                const int m = wm + mt * 16 + gid;
                af[mt][0] = As[(kb + tig) * ASTRIDE + m];
                af[mt][1] = As[(kb + tig) * ASTRIDE + m + 8];
                af[mt][2] = As[(kb + tig + 4) * ASTRIDE + m];
                af[mt][3] = As[(kb + tig + 4) * ASTRIDE + m + 8];
            }
            #pragma unroll
            for (int nt = 0; nt < 4; nt++) {
                const int n = wn + nt * 8 + gid;
                bf[nt][0] = Ws[(kb + tig) * ASTRIDE + n];
                bf[nt][1] = Ws[(kb + tig + 4) * ASTRIDE + n];
            }
            #pragma unroll
            for (int mt = 0; mt < 4; mt++)
                #pragma unroll
                for (int nt = 0; nt < 4; nt++)
                    mma8(acc[mt][nt], af[mt], bf[nt]);
        }
        __syncthreads();
    }

    // epilogue
    #pragma unroll
    for (int mt = 0; mt < 4; mt++) {
        const int m_lo = m0 + wm + mt * 16 + gid;
        const int m_hi = m_lo + 8;
        #pragma unroll
        for (int nt = 0; nt < 4; nt++) {
            const int n = n0 + wn + nt * 8 + 2 * tig;
            const float b0 = __ldg(bias + n), b1 = __ldg(bias + n + 1);
            float2 vlo, vhi;
            vlo.x = alpha * (acc[mt][nt][0] + b0);
            vlo.y = alpha * (acc[mt][nt][1] + b1);
            vhi.x = alpha * (acc[mt][nt][2] + b0);
            vhi.y = alpha * (acc[mt][nt][3] + b1);
            if (split) {
                const int h = n >> 6, d = n & (HD_ - 1);
                const int bb_lo = m_lo >> 11, t_lo = m_lo & (T_ - 1);
                const int bb_hi = m_hi >> 11, t_hi = m_hi & (T_ - 1);
                *(float2*)&out[((size_t)(bb_lo * H_ + h) * T_ + t_lo) * HD_ + d] = vlo;
                *(float2*)&out[((size_t)(bb_hi * H_ + h) * T_ + t_hi) * HD_ + d] = vhi;
            } else {
                *(float2*)&out[(size_t)m_lo * D_ + n] = vlo;
                *(float2*)&out[(size_t)m_hi * D_ + n] = vhi;
            }
        }
    }
}

// ---------------------------------------------------------------------------
// Tensor-core flash attention (tf32 mma.sync).
// CTA: 128 t-rows; 8 warps, each owns 16 t-rows. S streamed in 64-wide tiles.
// Q fragments in registers. Scores init = bias + mask. Online softmax on the
// C-fragment layout. P -> smem (tf32) -> A-fragments for PV.
// ---------------------------------------------------------------------------
#define KSTR 72   // Kst/Vs row stride (floats)
#define PSTR 68   // Pst row stride
#define ATTN_SMEM ((64*KSTR + 64*KSTR + 128*PSTR + 64) * 4)

__global__ __launch_bounds__(256) void attn_tc(
    const float* __restrict__ Q, const float* __restrict__ K,
    const float* __restrict__ V, const float* __restrict__ bias,
    const unsigned char* __restrict__ mask, float* __restrict__ Ctx)
{
    extern __shared__ uint32_t sm[];
    uint32_t* Kst = sm;                   // [64 d][KSTR] tf32, Kst[d][s]
    uint32_t* Vs  = Kst + 64 * KSTR;      // [64 s][KSTR] tf32, Vs[s][d]
    uint32_t* Pst = Vs  + 64 * KSTR;      // [128 t][PSTR] tf32
    float*   madd = (float*)(Pst + 128 * PSTR);

    const int tid = threadIdx.x;
    const int wid = tid >> 5, lane = tid & 31;
    const int gid = lane >> 2, tig = lane & 3;
    const int t0  = blockIdx.x * 128;
    const int h   = blockIdx.y, b = blockIdx.z;
    const int bh  = b * H_ + h;
    const int tw  = wid * 16;

    const float* Kb = K + (size_t)bh * S_ * HD_;
    const float* Vb = V + (size_t)bh * S_ * HD_;
    const float* Bp0 = bias + ((size_t)bh * T_ + t0 + tw) * (size_t)S_;

    // Q fragments (held for the whole kernel)
    uint32_t qa[8][4];
    {
        const float* Qb = Q + ((size_t)bh * T_ + t0 + tw) * HD_;
        #pragma unroll
        for (int ks = 0; ks < 8; ks++) {
            qa[ks][0] = f2tf32(Qb[(size_t)gid       * HD_ + ks * 8 + tig]);
            qa[ks][1] = f2tf32(Qb[(size_t)(gid + 8) * HD_ + ks * 8 + tig]);
            qa[ks][2] = f2tf32(Qb[(size_t)gid       * HD_ + ks * 8 + tig + 4]);
            qa[ks][3] = f2tf32(Qb[(size_t)(gid + 8) * HD_ + ks * 8 + tig + 4]);
        }
    }

    float oa[8][4] = {};
    float mr0 = -1e30f, mr1 = -1e30f, l0 = 0.0f, l1 = 0.0f;

    const int lrow = tid & 63;          // s-row for loads
    const int dq   = (tid >> 6) * 16;   // d segment base

    for (int s0 = 0; s0 < S_; s0 += 64) {
        __syncthreads();
        #pragma unroll
        for (int i = 0; i < 4; i++) {
            const int d0 = dq + i * 4;
            float4 kv = *(const float4*)(Kb + (size_t)(s0 + lrow) * HD_ + d0);
            Kst[(d0 + 0) * KSTR + lrow] = f2tf32(kv.x);
            Kst[(d0 + 1) * KSTR + lrow] = f2tf32(kv.y);
            Kst[(d0 + 2) * KSTR + lrow] = f2tf32(kv.z);
            Kst[(d0 + 3) * KSTR + lrow] = f2tf32(kv.w);
            float4 vv = *(const float4*)(Vb + (size_t)(s0 + lrow) * HD_ + d0);
            Vs[lrow * KSTR + d0 + 0] = f2tf32(vv.x);
            Vs[lrow * KSTR + d0 + 1] = f2tf32(vv.y);
            Vs[lrow * KSTR + d0 + 2] = f2tf32(vv.z);
            Vs[lrow * KSTR + d0 + 3] = f2tf32(vv.w);
        }
        if (tid < 64) madd[tid] = mask[b * S_ + s0 + tid] ? -1e30f : 0.0f;
        __syncthreads();

        // scores = bias + mask, then += Q K^T
        float sc[8][4];
        #pragma unroll
        for (int nt = 0; nt < 8; nt++) {
            const int cs = nt * 8 + 2 * tig;
            const float ma = madd[cs], mb = madd[cs + 1];
            float2 blo = *(const float2*)(Bp0 + (size_t)gid       * S_ + s0 + cs);
            float2 bhi = *(const float2*)(Bp0 + (size_t)(gid + 8) * S_ + s0 + cs);
            sc[nt][0] = blo.x + ma; sc[nt][1] = blo.y + mb;
            sc[nt][2] = bhi.x + ma; sc[nt][3] = bhi.y + mb;
        }
        #pragma unroll
        for (int ks = 0; ks < 8; ks++) {
            #pragma unroll
            for (int nt = 0; nt < 8; nt++) {
                uint32_t bf[2];
                bf[0] = Kst[(ks * 8 + tig)     * KSTR + nt * 8 + gid];
                bf[1] = Kst[(ks * 8 + tig + 4) * KSTR + nt * 8 + gid];
                mma8(sc[nt], qa[ks], bf);
            }
        }

        // online softmax (rows gid and gid+8; reduce across 4-lane tig group)
        float rm0 = -1e30f, rm1 = -1e30f;
        #pragma unroll
        for (int nt = 0; nt < 8; nt++) {
            rm0 = fmaxf(rm0, fmaxf(sc[nt][0], sc[nt][1]));
            rm1 = fmaxf(rm1, fmaxf(sc[nt][2], sc[nt][3]));
        }
        rm0 = fmaxf(rm0, __shfl_xor_sync(0xffffffffu, rm0, 1));
        rm0 = fmaxf(rm0, __shfl_xor_sync(0xffffffffu, rm0, 2));
        rm1 = fmaxf(rm1, __shfl_xor_sync(0xffffffffu, rm1, 1));
        rm1 = fmaxf(rm1, __shfl_xor_sync(0xffffffffu, rm1, 2));
        const float mn0 = fmaxf(mr0, rm0), mn1 = fmaxf(mr1, rm1);
        const float c0 = __expf(mr0 - mn0), c1 = __expf(mr1 - mn1);
        mr0 = mn0; mr1 = mn1;

        float ps0 = 0.0f, ps1 = 0.0f;
        #pragma unroll
        for (int nt = 0; nt < 8; nt++) {
            const float p00 = __expf(sc[nt][0] - mn0);
            const float p01 = __expf(sc[nt][1] - mn0);
            const float p10 = __expf(sc[nt][2] - mn1);
            const float p11 = __expf(sc[nt][3] - mn1);
            ps0 += p00 + p01; ps1 += p10 + p11;
            uint2 lo; lo.x = f2tf32(p00); lo.y = f2tf32(p01);
            uint2 hi; hi.x = f2tf32(p10); hi.y = f2tf32(p11);
            *(uint2*)&Pst[(tw + gid)     * PSTR + nt * 8 + 2 * tig] = lo;
            *(uint2*)&Pst[(tw + gid + 8) * PSTR + nt * 8 + 2 * tig] = hi;
        }
        ps0 += __shfl_xor_sync(0xffffffffu, ps0, 1);
        ps0 += __shfl_xor_sync(0xffffffffu, ps0, 2);
        ps1 += __shfl_xor_sync(0xffffffffu, ps1, 1);
        ps1 += __shfl_xor_sync(0xffffffffu, ps1, 2);
        l0 = l0 * c0 + ps0;
        l1 = l1 * c1 + ps1;
        #pragma unroll
        for (int nt = 0; nt < 8; nt++) {
            oa[nt][0] *= c0; oa[nt][1] *= c0;
            oa[nt][2] *= c1; oa[nt][3] *= c1;
        }
        __syncwarp();

        // O += P V (P rows are warp-private)
        #pragma unroll
        for (int ks = 0; ks < 8; ks++) {
            uint32_t pf[4];
            pf[0] = Pst[(tw + gid)     * PSTR + ks * 8 + tig];
            pf[1] = Pst[(tw + gid + 8) * PSTR + ks * 8 + tig];
            pf[2] = Pst[(tw + gid)     * PSTR + ks * 8 + tig + 4];
            pf[3] = Pst[(tw + gid + 8) * PSTR + ks * 8 + tig + 4];
            #pragma unroll
            for (int nt = 0; nt < 8; nt++) {
                uint32_t bf[2];
                bf[0] = Vs[(ks * 8 + tig)     * KSTR + nt * 8 + gid];
                bf[1] = Vs[(ks * 8 + tig + 4) * KSTR + nt * 8 + gid];
                mma8(oa[nt], pf, bf);
            }
        }
    }

    // normalize + write context [B,T,D]
    const float i0 = 1.0f / l0, i1 = 1.0f / l1;
    float* Cb = Ctx + ((size_t)b * T_ + t0 + tw) * D_ + h * HD_;
    #pragma unroll
    for (int nt = 0; nt < 8; nt++) {
        float2 lo, hi;
        lo.x = oa[nt][0] * i0; lo.y = oa[nt][1] * i0;
        hi.x = oa[nt][2] * i1; hi.y = oa[nt][3] * i1;
        *(float2*)(Cb + (size_t)gid       * D_ + nt * 8 + 2 * tig) = lo;
        *(float2*)(Cb + (size_t)(gid + 8) * D_ + nt * 8 + 2 * tig) = hi;
    }
}

// ---------------------------------------------------------------------------
extern "C" void kernel_launch(void* const* d_in, const int* in_sizes, int n_in,
                              void* d_out, int out_size)
{
    (void)in_sizes; (void)n_in; (void)out_size;
    const float* query = (const float*)d_in[0];
    const float* key   = (const float*)d_in[1];
    const float* value = (const float*)d_in[2];
    const float* bias  = (const float*)d_in[3];
    const unsigned char* mask = (const unsigned char*)d_in[4];
    const float* Wq = (const float*)d_in[5];
    const float* bq = (const float*)d_in[6];
    const float* Wk = (const float*)d_in[7];
    const float* bk = (const float*)d_in[8];
    const float* Wv = (const float*)d_in[9];
    const float* bv = (const float*)d_in[10];
    const float* Wo = (const float*)d_in[11];
    const float* bo = (const float*)d_in[12];

    float *qp, *kp, *vp, *cp;
    cudaGetSymbolAddress((void**)&qp, g_Q);
    cudaGetSymbolAddress((void**)&kp, g_K);
    cudaGetSymbolAddress((void**)&vp, g_V);
    cudaGetSymbolAddress((void**)&cp, g_C);

    cudaFuncSetAttribute(attn_tc, cudaFuncAttributeMaxDynamicSharedMemorySize,
                         ATTN_SMEM);

    const dim3 gemmGrid(D_ / 128, (B_ * T_) / 128);  // (8, 32)
    const float qscale = 0.125f;  // 1/sqrt(HD), folded into Q projection

    gemm_tc<<<gemmGrid, 256>>>(query, Wq, bq, qp, 1, qscale);
    gemm_tc<<<gemmGrid, 256>>>(key,   Wk, bk, kp, 1, 1.0f);
    gemm_tc<<<gemmGrid, 256>>>(value, Wv, bv, vp, 1, 1.0f);

    attn_tc<<<dim3(T_ / 128, H_, B_), 256, ATTN_SMEM>>>(qp, kp, vp, bias, mask, cp);

    gemm_tc<<<gemmGrid, 256>>>(cp, Wo, bo, (float*)d_out, 0, 1.0f);
}

// round 4
// speedup vs baseline: 3.0126x; 1.5759x over previous
#include <cuda_runtime.h>
#include <cuda_fp16.h>
#include <cstdint>

#define B_  2
#define H_  16
#define T_  2048
#define S_  2048
#define D_  1024
#define HD_ 64

// Scratch (allocation-free rule: device globals)
__device__ float g_Q[B_*H_*T_*HD_];   // head-split, pre-scaled by 1/sqrt(HD)
__device__ float g_K[B_*H_*S_*HD_];
__device__ float g_V[B_*H_*S_*HD_];
__device__ float g_C[B_*T_*D_];       // attention context, [B,T,D]

// ---------------------------------------------------------------------------
// helpers (baseline PTX only — works at compute_103 virtual arch)
// ---------------------------------------------------------------------------
__device__ __forceinline__ uint32_t smem_u32(const void* p) {
    uint32_t a;
    asm("{ .reg .u64 t; cvta.to.shared.u64 t, %1; cvt.u32.u64 %0, t; }"
        : "=r"(a) : "l"(p));
    return a;
}
__device__ __forceinline__ uint32_t h2(float lo, float hi) {
    __half2 h = __floats2half2_rn(lo, hi);
    return *(uint32_t*)&h;
}
// D += A(16x16 f16) * B(16x8 f16); C f32 in place.
__device__ __forceinline__ void mma16(float* d, const uint32_t* a,
                                      uint32_t b0, uint32_t b1) {
    asm volatile("mma.sync.aligned.m16n8k16.row.col.f32.f16.f16.f32 "
                 "{%0,%1,%2,%3}, {%4,%5,%6,%7}, {%8,%9}, {%0,%1,%2,%3};"
                 : "+f"(d[0]), "+f"(d[1]), "+f"(d[2]), "+f"(d[3])
                 : "r"(a[0]), "r"(a[1]), "r"(a[2]), "r"(a[3]),
                   "r"(b0), "r"(b1));
}
#define LDSM4(r0, r1, r2, r3, addr)                                            \
    asm volatile("ldmatrix.sync.aligned.m8n8.x4.shared.b16 {%0,%1,%2,%3}, [%4];" \
                 : "=r"(r0), "=r"(r1), "=r"(r2), "=r"(r3) : "r"(addr))
#define LDSM4T(r0, r1, r2, r3, addr)                                           \
    asm volatile("ldmatrix.sync.aligned.m8n8.x4.trans.shared.b16 {%0,%1,%2,%3}, [%4];" \
                 : "=r"(r0), "=r"(r1), "=r"(r2), "=r"(r3) : "r"(addr))

// ---------------------------------------------------------------------------
// fp16 tensor-core GEMM: out = alpha * (A[M,1024] @ W[N,1024]^T + bias[N])
// CTA 128x128, 8 warps (64x32 warp tiles), K-tile 32, reg prefetch, ldmatrix.
// Smem rows = 64B (32 halves), swizzle: chunk ^= (row>>1)&3.
// ---------------------------------------------------------------------------
__global__ __launch_bounds__(256) void gemm_tc(
    const float* __restrict__ A, const float* __restrict__ W,
    const float* __restrict__ bias, float* __restrict__ out,
    int split, float alpha)
{
    __shared__ __align__(16) char smA[128 * 64];
    __shared__ __align__(16) char smB[128 * 64];
    const uint32_t sA = smem_u32(smA), sB = smem_u32(smB);

    const int tid  = threadIdx.x;
    const int wid  = tid >> 5, lane = tid & 31;
    const int gid  = lane >> 2, tig = lane & 3;
    const int m0   = blockIdx.y * 128, n0 = blockIdx.x * 128;
    const int wm   = (wid & 1) * 64, wn = (wid >> 1) * 32;

    // ldmatrix lane addressing: A-pattern (rowbit=lane>>3, chunkbit=lane>>4),
    // B-pattern (rowbit=lane>>4, chunkbit=lane>>3)
    const int rA = (lane & 7) + ((lane >> 3) & 1) * 8, cA = (lane >> 4) & 1;
    const int rB = (lane & 7) + ((lane >> 4) & 1) * 8, cB = (lane >> 3) & 1;
    const int xA = (rA >> 1) & 3, xB = (rB >> 1) & 3;

    const int lrow = tid & 127;
    const int lks  = (tid >> 7) * 16;

    const float* Ap = A + (size_t)(m0 + lrow) * 1024 + lks;
    const float* Wp = W + (size_t)(n0 + lrow) * 1024 + lks;

    float4 pa[4], pw[4];
    #pragma unroll
    for (int q = 0; q < 4; q++) {
        pa[q] = *(const float4*)(Ap + q * 4);
        pw[q] = *(const float4*)(Wp + q * 4);
    }

    float acc[4][4][4] = {};

    for (int kt = 0; kt < 32; kt++) {
        #pragma unroll
        for (int q = 0; q < 4; q++) {
            const int k = lks + q * 4;
            const uint32_t byte = lrow * 64
                + ((((k >> 3) ^ ((lrow >> 1) & 3)) << 4) | (((k >> 2) & 1) << 3));
            uint2 ua; ua.x = h2(pa[q].x, pa[q].y); ua.y = h2(pa[q].z, pa[q].w);
            *(uint2*)(smA + byte) = ua;
            uint2 uw; uw.x = h2(pw[q].x, pw[q].y); uw.y = h2(pw[q].z, pw[q].w);
            *(uint2*)(smB + byte) = uw;
        }
        __syncthreads();

        if (kt < 31) {
            #pragma unroll
            for (int q = 0; q < 4; q++) {
                pa[q] = *(const float4*)(Ap + (kt + 1) * 32 + q * 4);
                pw[q] = *(const float4*)(Wp + (kt + 1) * 32 + q * 4);
            }
        }

        #pragma unroll
        for (int kb = 0; kb < 2; kb++) {
            uint32_t af[4][4], bf[4][2];
            #pragma unroll
            for (int mt = 0; mt < 4; mt++) {
                const uint32_t addr = sA + (wm + mt * 16 + rA) * 64
                                    + (((kb * 2 + cA) ^ xA) << 4);
                LDSM4(af[mt][0], af[mt][1], af[mt][2], af[mt][3], addr);
            }
            #pragma unroll
            for (int ntp = 0; ntp < 2; ntp++) {
                uint32_t r0, r1, r2, r3;
                const uint32_t addr = sB + (wn + ntp * 16 + rB) * 64
                                    + (((kb * 2 + cB) ^ xB) << 4);
                LDSM4(r0, r1, r2, r3, addr);
                bf[2*ntp][0] = r0; bf[2*ntp][1] = r1;
                bf[2*ntp+1][0] = r2; bf[2*ntp+1][1] = r3;
            }
            #pragma unroll
            for (int mt = 0; mt < 4; mt++)
                #pragma unroll
                for (int nt = 0; nt < 4; nt++)
                    mma16(acc[mt][nt], af[mt], bf[nt][0], bf[nt][1]);
        }
        __syncthreads();
    }

    // epilogue
    #pragma unroll
    for (int mt = 0; mt < 4; mt++) {
        const int m_lo = m0 + wm + mt * 16 + gid;
        const int m_hi = m_lo + 8;
        #pragma unroll
        for (int nt = 0; nt < 4; nt++) {
            const int n = n0 + wn + nt * 8 + 2 * tig;
            const float b0 = __ldg(bias + n), b1 = __ldg(bias + n + 1);
            float2 vlo, vhi;
            vlo.x = alpha * (acc[mt][nt][0] + b0);
            vlo.y = alpha * (acc[mt][nt][1] + b1);
            vhi.x = alpha * (acc[mt][nt][2] + b0);
            vhi.y = alpha * (acc[mt][nt][3] + b1);
            if (split) {
                const int h = n >> 6, d = n & (HD_ - 1);
                const int bb_lo = m_lo >> 11, t_lo = m_lo & (T_ - 1);
                const int bb_hi = m_hi >> 11, t_hi = m_hi & (T_ - 1);
                *(float2*)&out[((size_t)(bb_lo * H_ + h) * T_ + t_lo) * HD_ + d] = vlo;
                *(float2*)&out[((size_t)(bb_hi * H_ + h) * T_ + t_hi) * HD_ + d] = vhi;
            } else {
                *(float2*)&out[(size_t)m_lo * D_ + n] = vlo;
                *(float2*)&out[(size_t)m_hi * D_ + n] = vhi;
            }
        }
    }
}

// ---------------------------------------------------------------------------
// fp16 tensor-core flash attention.
// CTA: 128 t-rows, 8 warps x 16 rows; S in 64-wide tiles. Q frags in regs,
// K/V in smem (SW128-style swizzle, 128B rows), P stays in registers
// (score C-frag layout == PV A-frag layout). fp32 softmax + accumulators.
// ---------------------------------------------------------------------------
__global__ __launch_bounds__(256, 2) void attn_tc(
    const float* __restrict__ Q, const float* __restrict__ K,
    const float* __restrict__ V, const float* __restrict__ bias,
    const unsigned char* __restrict__ mask, float* __restrict__ Ctx)
{
    __shared__ __align__(16) char Ksm[64 * 128];
    __shared__ __align__(16) char Vsm[64 * 128];
    __shared__ float madd[64];
    const uint32_t sK = smem_u32(Ksm), sV = smem_u32(Vsm);

    const int tid = threadIdx.x;
    const int wid = tid >> 5, lane = tid & 31;
    const int gid = lane >> 2, tig = lane & 3;
    const int t0  = blockIdx.x * 128;
    const int h   = blockIdx.y, b = blockIdx.z;
    const int bh  = b * H_ + h;
    const int tw  = wid * 16;

    const int rA = (lane & 7) + ((lane >> 3) & 1) * 8, cA = (lane >> 4) & 1;
    const int rB = (lane & 7) + ((lane >> 4) & 1) * 8, cB = (lane >> 3) & 1;
    const int x_ = lane & 7;  // swizzle xor (row & 7) for both patterns

    const float* Kb  = K + (size_t)bh * S_ * HD_;
    const float* Vb  = V + (size_t)bh * S_ * HD_;
    const float* Bp0 = bias + ((size_t)bh * T_ + t0 + tw) * (size_t)S_;

    // Q A-fragments, fp16, held in registers for the whole kernel
    uint32_t qa[4][4];
    {
        const float* Qb = Q + ((size_t)bh * T_ + t0 + tw) * HD_;
        #pragma unroll
        for (int ks = 0; ks < 4; ks++) {
            const int k = ks * 16 + 2 * tig;
            float2 v0 = *(const float2*)(Qb + (size_t)gid       * HD_ + k);
            float2 v1 = *(const float2*)(Qb + (size_t)(gid + 8) * HD_ + k);
            float2 v2 = *(const float2*)(Qb + (size_t)gid       * HD_ + k + 8);
            float2 v3 = *(const float2*)(Qb + (size_t)(gid + 8) * HD_ + k + 8);
            qa[ks][0] = h2(v0.x, v0.y);
            qa[ks][1] = h2(v1.x, v1.y);
            qa[ks][2] = h2(v2.x, v2.y);
            qa[ks][3] = h2(v3.x, v3.y);
        }
    }

    float oa[8][4] = {};
    float mr0 = -1e30f, mr1 = -1e30f, l0 = 0.0f, l1 = 0.0f;

    const int lrow = tid & 63;          // s-row for cooperative loads
    const int dq   = (tid >> 6) * 16;   // d segment base

    for (int s0 = 0; s0 < S_; s0 += 64) {
        __syncthreads();
        #pragma unroll
        for (int i = 0; i < 4; i++) {
            const int d0 = dq + i * 4;
            const uint32_t byte = lrow * 128
                + ((((d0 >> 3) ^ (lrow & 7)) << 4) | (((d0 >> 2) & 1) << 3));
            float4 kv = *(const float4*)(Kb + (size_t)(s0 + lrow) * HD_ + d0);
            uint2 uk; uk.x = h2(kv.x, kv.y); uk.y = h2(kv.z, kv.w);
            *(uint2*)(Ksm + byte) = uk;
            float4 vv = *(const float4*)(Vb + (size_t)(s0 + lrow) * HD_ + d0);
            uint2 uv; uv.x = h2(vv.x, vv.y); uv.y = h2(vv.z, vv.w);
            *(uint2*)(Vsm + byte) = uv;
        }
        if (tid < 64) madd[tid] = mask[b * S_ + s0 + tid] ? -1e30f : 0.0f;
        __syncthreads();

        // scores = bias + mask, then += Q K^T   (k-dim = d, n-dim = s)
        float sc[8][4];
        #pragma unroll
        for (int nt = 0; nt < 8; nt++) {
            const int cs = nt * 8 + 2 * tig;
            const float ma = madd[cs], mb = madd[cs + 1];
            float2 blo = *(const float2*)(Bp0 + (size_t)gid       * S_ + s0 + cs);
            float2 bhi = *(const float2*)(Bp0 + (size_t)(gid + 8) * S_ + s0 + cs);
            sc[nt][0] = blo.x + ma; sc[nt][1] = blo.y + mb;
            sc[nt][2] = bhi.x + ma; sc[nt][3] = bhi.y + mb;
        }
        #pragma unroll
        for (int ks = 0; ks < 4; ks++) {
            #pragma unroll
            for (int ntp = 0; ntp < 4; ntp++) {
                uint32_t r0, r1, r2, r3;
                const uint32_t addr = sK + (ntp * 16 + rB) * 128
                                    + (((2 * ks + cB) ^ x_) << 4);
                LDSM4(r0, r1, r2, r3, addr);
                mma16(sc[2*ntp],   qa[ks], r0, r1);
                mma16(sc[2*ntp+1], qa[ks], r2, r3);
            }
        }

        // online softmax (rows gid / gid+8; reduce across the 4 tig lanes)
        float rm0 = -1e30f, rm1 = -1e30f;
        #pragma unroll
        for (int nt = 0; nt < 8; nt++) {
            rm0 = fmaxf(rm0, fmaxf(sc[nt][0], sc[nt][1]));
            rm1 = fmaxf(rm1, fmaxf(sc[nt][2], sc[nt][3]));
        }
        rm0 = fmaxf(rm0, __shfl_xor_sync(0xffffffffu, rm0, 1));
        rm0 = fmaxf(rm0, __shfl_xor_sync(0xffffffffu, rm0, 2));
        rm1 = fmaxf(rm1, __shfl_xor_sync(0xffffffffu, rm1, 1));
        rm1 = fmaxf(rm1, __shfl_xor_sync(0xffffffffu, rm1, 2));
        const float mn0 = fmaxf(mr0, rm0), mn1 = fmaxf(mr1, rm1);
        const float c0 = __expf(mr0 - mn0), c1 = __expf(mr1 - mn1);
        mr0 = mn0; mr1 = mn1;

        // P in registers, packed straight into PV A-fragment layout
        uint32_t ph[8][2];
        float ps0 = 0.0f, ps1 = 0.0f;
        #pragma unroll
        for (int nt = 0; nt < 8; nt++) {
            const float p00 = __expf(sc[nt][0] - mn0);
            const float p01 = __expf(sc[nt][1] - mn0);
            const float p10 = __expf(sc[nt][2] - mn1);
            const float p11 = __expf(sc[nt][3] - mn1);
            ps0 += p00 + p01; ps1 += p10 + p11;
            ph[nt][0] = h2(p00, p01);
            ph[nt][1] = h2(p10, p11);
        }
        ps0 += __shfl_xor_sync(0xffffffffu, ps0, 1);
        ps0 += __shfl_xor_sync(0xffffffffu, ps0, 2);
        ps1 += __shfl_xor_sync(0xffffffffu, ps1, 1);
        ps1 += __shfl_xor_sync(0xffffffffu, ps1, 2);
        l0 = l0 * c0 + ps0;
        l1 = l1 * c1 + ps1;
        #pragma unroll
        for (int nt = 0; nt < 8; nt++) {
            oa[nt][0] *= c0; oa[nt][1] *= c0;
            oa[nt][2] *= c1; oa[nt][3] *= c1;
        }

        // O += P V   (k-dim = s, n-dim = d; V frags via ldmatrix.trans)
        #pragma unroll
        for (int ks2 = 0; ks2 < 4; ks2++) {
            uint32_t pf[4];
            pf[0] = ph[2*ks2][0];   pf[1] = ph[2*ks2][1];
            pf[2] = ph[2*ks2+1][0]; pf[3] = ph[2*ks2+1][1];
            #pragma unroll
            for (int ntp = 0; ntp < 4; ntp++) {
                uint32_t r0, r1, r2, r3;
                const uint32_t addr = sV + (ks2 * 16 + rA) * 128
                                    + (((ntp * 2 + cA) ^ x_) << 4);
                LDSM4T(r0, r1, r2, r3, addr);
                mma16(oa[2*ntp],   pf, r0, r1);
                mma16(oa[2*ntp+1], pf, r2, r3);
            }
        }
    }

    // normalize + write context [B,T,D]
    const float i0 = 1.0f / l0, i1 = 1.0f / l1;
    float* Cb = Ctx + ((size_t)b * T_ + t0 + tw) * D_ + h * HD_;
    #pragma unroll
    for (int nt = 0; nt < 8; nt++) {
        float2 lo, hi;
        lo.x = oa[nt][0] * i0; lo.y = oa[nt][1] * i0;
        hi.x = oa[nt][2] * i1; hi.y = oa[nt][3] * i1;
        *(float2*)(Cb + (size_t)gid       * D_ + nt * 8 + 2 * tig) = lo;
        *(float2*)(Cb + (size_t)(gid + 8) * D_ + nt * 8 + 2 * tig) = hi;
    }
}

// ---------------------------------------------------------------------------
extern "C" void kernel_launch(void* const* d_in, const int* in_sizes, int n_in,
                              void* d_out, int out_size)
{
    (void)in_sizes; (void)n_in; (void)out_size;
    const float* query = (const float*)d_in[0];
    const float* key   = (const float*)d_in[1];
    const float* value = (const float*)d_in[2];
    const float* bias  = (const float*)d_in[3];
    const unsigned char* mask = (const unsigned char*)d_in[4];
    const float* Wq = (const float*)d_in[5];
    const float* bq = (const float*)d_in[6];
    const float* Wk = (const float*)d_in[7];
    const float* bk = (const float*)d_in[8];
    const float* Wv = (const float*)d_in[9];
    const float* bv = (const float*)d_in[10];
    const float* Wo = (const float*)d_in[11];
    const float* bo = (const float*)d_in[12];

    float *qp, *kp, *vp, *cp;
    cudaGetSymbolAddress((void**)&qp, g_Q);
    cudaGetSymbolAddress((void**)&kp, g_K);
    cudaGetSymbolAddress((void**)&vp, g_V);
    cudaGetSymbolAddress((void**)&cp, g_C);

    const dim3 gemmGrid(D_ / 128, (B_ * T_) / 128);  // (8, 32)
    const float qscale = 0.125f;  // 1/sqrt(HD), folded into Q projection

    gemm_tc<<<gemmGrid, 256>>>(query, Wq, bq, qp, 1, qscale);
    gemm_tc<<<gemmGrid, 256>>>(key,   Wk, bk, kp, 1, 1.0f);
    gemm_tc<<<gemmGrid, 256>>>(value, Wv, bv, vp, 1, 1.0f);

    attn_tc<<<dim3(T_ / 128, H_, B_), 256>>>(qp, kp, vp, bias, mask, cp);

    gemm_tc<<<gemmGrid, 256>>>(cp, Wo, bo, (float*)d_out, 0, 1.0f);
}

// round 5
// speedup vs baseline: 5.3061x; 1.7613x over previous
#include <cuda_runtime.h>
#include <cuda_fp16.h>
#include <cstdint>

#define B_  2
#define H_  16
#define T_  2048
#define S_  2048
#define D_  1024
#define HD_ 64

// fp16 scratch (allocation-free rule: device globals)
__device__ __half g_qh[B_*T_*D_];
__device__ __half g_kh[B_*T_*D_];
__device__ __half g_vh[B_*T_*D_];
__device__ __half g_Wqh[D_*D_];
__device__ __half g_Wkh[D_*D_];
__device__ __half g_Wvh[D_*D_];
__device__ __half g_Woh[D_*D_];
__device__ __half g_Q[B_*H_*T_*HD_];   // head-split, pre-scaled by 1/sqrt(HD)
__device__ __half g_K[B_*H_*S_*HD_];
__device__ __half g_V[B_*H_*S_*HD_];
__device__ __half g_Ch[B_*T_*D_];      // attention context, [B,T,D]

// ---------------------------------------------------------------------------
// helpers (baseline PTX only — works at compute_103 virtual arch)
// ---------------------------------------------------------------------------
__device__ __forceinline__ uint32_t smem_u32(const void* p) {
    uint32_t a;
    asm("{ .reg .u64 t; cvta.to.shared.u64 t, %1; cvt.u32.u64 %0, t; }"
        : "=r"(a) : "l"(p));
    return a;
}
__device__ __forceinline__ uint32_t h2(float lo, float hi) {
    __half2 h = __floats2half2_rn(lo, hi);
    return *(uint32_t*)&h;
}
__device__ __forceinline__ void mma16(float* d, const uint32_t* a,
                                      uint32_t b0, uint32_t b1) {
    asm volatile("mma.sync.aligned.m16n8k16.row.col.f32.f16.f16.f32 "
                 "{%0,%1,%2,%3}, {%4,%5,%6,%7}, {%8,%9}, {%0,%1,%2,%3};"
                 : "+f"(d[0]), "+f"(d[1]), "+f"(d[2]), "+f"(d[3])
                 : "r"(a[0]), "r"(a[1]), "r"(a[2]), "r"(a[3]),
                   "r"(b0), "r"(b1));
}
#define LDSM4(r0, r1, r2, r3, addr)                                            \
    asm volatile("ldmatrix.sync.aligned.m8n8.x4.shared.b16 {%0,%1,%2,%3}, [%4];" \
                 : "=r"(r0), "=r"(r1), "=r"(r2), "=r"(r3) : "r"(addr))
#define LDSM4T(r0, r1, r2, r3, addr)                                           \
    asm volatile("ldmatrix.sync.aligned.m8n8.x4.trans.shared.b16 {%0,%1,%2,%3}, [%4];" \
                 : "=r"(r0), "=r"(r1), "=r"(r2), "=r"(r3) : "r"(addr))
#define CP16(dst, src)                                                         \
    asm volatile("cp.async.cg.shared.global [%0], [%1], 16;" :: "r"(dst), "l"(src))
#define CP_COMMIT() asm volatile("cp.async.commit_group;")
#define CP_WAIT1()  asm volatile("cp.async.wait_group 1;")
#define CP_WAIT0()  asm volatile("cp.async.wait_group 0;")

// ---------------------------------------------------------------------------
// fp32 -> fp16 conversion (vectorized)
// ---------------------------------------------------------------------------
__global__ __launch_bounds__(256) void cvt_h(
    const float4* __restrict__ in, uint2* __restrict__ out, int n4)
{
    const int i = blockIdx.x * blockDim.x + threadIdx.x;
    if (i < n4) {
        float4 v = in[i];
        uint2 o; o.x = h2(v.x, v.y); o.y = h2(v.z, v.w);
        out[i] = o;
    }
}

// ---------------------------------------------------------------------------
// fp16 GEMM: out = alpha * (A[M,1024] @ W[N,1024]^T + bias[N])
// CTA 128x128, 8 warps (64x32), K-tile 64 halves (128B rows), cp.async
// double-buffered, ldmatrix fragments. split=1: fp16 head-split out;
// split=0: fp32 plain out.
// ---------------------------------------------------------------------------
#define G_STAGE 32768  // A 16KB + B 16KB per stage
#define G_SMEM  (2 * G_STAGE)
#define G_NT    16     // 1024 / 64

__global__ __launch_bounds__(256, 2) void gemm_h(
    const __half* __restrict__ A, const __half* __restrict__ W,
    const float* __restrict__ bias, void* __restrict__ outp,
    int split, float alpha)
{
    extern __shared__ __align__(16) char dsm[];
    const uint32_t sb = smem_u32(dsm);

    const int tid  = threadIdx.x;
    const int wid  = tid >> 5, lane = tid & 31;
    const int gid  = lane >> 2, tig = lane & 3;
    const int m0   = blockIdx.y * 128, n0 = blockIdx.x * 128;
    const int wm   = (wid & 1) * 64, wn = (wid >> 1) * 32;

    const int rA = (lane & 7) + ((lane >> 3) & 1) * 8, cA = (lane >> 4) & 1;
    const int rB = (lane & 7) + ((lane >> 4) & 1) * 8, cB = (lane >> 3) & 1;
    const int xA = rA & 7, xB = rB & 7;

    // copy mapping: 128 rows x 8 chunks (16B) per matrix; 4 chunks/thread each
    const int crow = tid >> 1;
    const int cc0  = (tid & 1) * 4;
    const __half* Asrc = A + (size_t)(m0 + crow) * 1024;
    const __half* Wsrc = W + (size_t)(n0 + crow) * 1024;
    const uint32_t dstrow = sb + (uint32_t)crow * 128;

    // stage issue
    #define G_ISSUE(kt, s) do {                                                \
        const uint32_t _st = (uint32_t)(s) * G_STAGE;                          \
        _Pragma("unroll")                                                      \
        for (int _c = 0; _c < 4; _c++) {                                       \
            const int c = cc0 + _c;                                            \
            const uint32_t d = dstrow + _st + (uint32_t)((c ^ (crow & 7)) << 4); \
            CP16(d,           Asrc + (kt) * 64 + c * 8);                       \
            CP16(d + 16384u,  Wsrc + (kt) * 64 + c * 8);                       \
        }                                                                      \
    } while (0)

    float acc[4][4][4] = {};

    G_ISSUE(0, 0);
    CP_COMMIT();

    for (int kt = 0; kt < G_NT; kt++) {
        const int s = kt & 1;
        if (kt + 1 < G_NT) { G_ISSUE(kt + 1, s ^ 1); CP_COMMIT(); CP_WAIT1(); }
        else               { CP_WAIT0(); }
        __syncthreads();

        const uint32_t aST = sb + (uint32_t)s * G_STAGE;
        const uint32_t bST = aST + 16384u;

        #pragma unroll
        for (int ks = 0; ks < 4; ks++) {
            uint32_t af[4][4], bf[4][2];
            #pragma unroll
            for (int mt = 0; mt < 4; mt++) {
                const uint32_t addr = aST + (wm + mt * 16 + rA) * 128
                                    + ((((ks << 1) | cA) ^ xA) << 4);
                LDSM4(af[mt][0], af[mt][1], af[mt][2], af[mt][3], addr);
            }
            #pragma unroll
            for (int ntp = 0; ntp < 2; ntp++) {
                uint32_t r0, r1, r2, r3;
                const uint32_t addr = bST + (wn + ntp * 16 + rB) * 128
                                    + ((((ks << 1) | cB) ^ xB) << 4);
                LDSM4(r0, r1, r2, r3, addr);
                bf[2*ntp][0] = r0; bf[2*ntp][1] = r1;
                bf[2*ntp+1][0] = r2; bf[2*ntp+1][1] = r3;
            }
            #pragma unroll
            for (int mt = 0; mt < 4; mt++)
                #pragma unroll
                for (int nt = 0; nt < 4; nt++)
                    mma16(acc[mt][nt], af[mt], bf[nt][0], bf[nt][1]);
        }
        __syncthreads();
    }

    // epilogue
    #pragma unroll
    for (int mt = 0; mt < 4; mt++) {
        const int m_lo = m0 + wm + mt * 16 + gid;
        const int m_hi = m_lo + 8;
        #pragma unroll
        for (int nt = 0; nt < 4; nt++) {
            const int n = n0 + wn + nt * 8 + 2 * tig;
            const float b0 = __ldg(bias + n), b1 = __ldg(bias + n + 1);
            const float v00 = alpha * (acc[mt][nt][0] + b0);
            const float v01 = alpha * (acc[mt][nt][1] + b1);
            const float v10 = alpha * (acc[mt][nt][2] + b0);
            const float v11 = alpha * (acc[mt][nt][3] + b1);
            if (split) {
                __half* o = (__half*)outp;
                const int hh = n >> 6, d = n & (HD_ - 1);
                const int bb_lo = m_lo >> 11, t_lo = m_lo & (T_ - 1);
                const int bb_hi = m_hi >> 11, t_hi = m_hi & (T_ - 1);
                *(uint32_t*)&o[((size_t)(bb_lo * H_ + hh) * T_ + t_lo) * HD_ + d] = h2(v00, v01);
                *(uint32_t*)&o[((size_t)(bb_hi * H_ + hh) * T_ + t_hi) * HD_ + d] = h2(v10, v11);
            } else {
                float* o = (float*)outp;
                float2 vlo; vlo.x = v00; vlo.y = v01;
                float2 vhi; vhi.x = v10; vhi.y = v11;
                *(float2*)&o[(size_t)m_lo * D_ + n] = vlo;
                *(float2*)&o[(size_t)m_hi * D_ + n] = vhi;
            }
        }
    }
}

// ---------------------------------------------------------------------------
// fp16 flash attention, cp.async double-buffered K/V.
// CTA: 128 t-rows, 8 warps x 16 rows; S in 64-wide tiles. Q frags in regs,
// P stays in registers. fp32 softmax + accumulators. Ctx out fp16.
// ---------------------------------------------------------------------------
#define KV_STAGE 8192   // one 64x128B tile

__global__ __launch_bounds__(256, 2) void attn_tc(
    const __half* __restrict__ Q, const __half* __restrict__ K,
    const __half* __restrict__ V, const float* __restrict__ bias,
    const unsigned char* __restrict__ mask, __half* __restrict__ Ctx)
{
    __shared__ __align__(16) char Ksm[2 * KV_STAGE];
    __shared__ __align__(16) char Vsm[2 * KV_STAGE];
    __shared__ float madd[2][64];
    const uint32_t sK = smem_u32(Ksm), sV = smem_u32(Vsm);

    const int tid = threadIdx.x;
    const int wid = tid >> 5, lane = tid & 31;
    const int gid = lane >> 2, tig = lane & 3;
    const int t0  = blockIdx.x * 128;
    const int h   = blockIdx.y, b = blockIdx.z;
    const int bh  = b * H_ + h;
    const int tw  = wid * 16;

    const int rA = (lane & 7) + ((lane >> 3) & 1) * 8, cA = (lane >> 4) & 1;
    const int rB = (lane & 7) + ((lane >> 4) & 1) * 8, cB = (lane >> 3) & 1;
    const int x_ = lane & 7;

    const __half* Kb  = K + (size_t)bh * S_ * HD_;
    const __half* Vb  = V + (size_t)bh * S_ * HD_;
    const float*  Bp0 = bias + ((size_t)bh * T_ + t0 + tw) * (size_t)S_;

    // copy mapping: 64 rows x 8 chunks per matrix; 2 chunks/thread per matrix
    const int crow = tid >> 2;
    const int cc0  = (tid & 3) * 2;
    const uint32_t kdst = sK + (uint32_t)crow * 128;
    const uint32_t vdst = sV + (uint32_t)crow * 128;

    #define KV_ISSUE(it, s) do {                                               \
        const uint32_t _st = (uint32_t)(s) * KV_STAGE;                         \
        const int _s0 = (it) * 64;                                             \
        _Pragma("unroll")                                                      \
        for (int _c = 0; _c < 2; _c++) {                                       \
            const int c = cc0 + _c;                                            \
            const uint32_t off = _st + (uint32_t)((c ^ (crow & 7)) << 4);      \
            CP16(kdst + off, Kb + (size_t)(_s0 + crow) * HD_ + c * 8);         \
            CP16(vdst + off, Vb + (size_t)(_s0 + crow) * HD_ + c * 8);         \
        }                                                                      \
        if (tid < 64) madd[s][tid] = mask[b * S_ + _s0 + tid] ? -1e30f : 0.0f; \
    } while (0)

    // Q A-fragments (fp16 direct loads), held for the whole kernel
    uint32_t qa[4][4];
    {
        const __half* Qb = Q + ((size_t)bh * T_ + t0 + tw) * HD_;
        #pragma unroll
        for (int ks = 0; ks < 4; ks++) {
            const int k = ks * 16 + 2 * tig;
            qa[ks][0] = *(const uint32_t*)(Qb + (size_t)gid       * HD_ + k);
            qa[ks][1] = *(const uint32_t*)(Qb + (size_t)(gid + 8) * HD_ + k);
            qa[ks][2] = *(const uint32_t*)(Qb + (size_t)gid       * HD_ + k + 8);
            qa[ks][3] = *(const uint32_t*)(Qb + (size_t)(gid + 8) * HD_ + k + 8);
        }
    }

    float oa[8][4] = {};
    float mr0 = -1e30f, mr1 = -1e30f, l0 = 0.0f, l1 = 0.0f;

    KV_ISSUE(0, 0);
    CP_COMMIT();

    for (int it = 0; it < S_ / 64; it++) {
        const int s = it & 1;
        const int s0 = it * 64;
        if (it + 1 < S_ / 64) { KV_ISSUE(it + 1, s ^ 1); CP_COMMIT(); CP_WAIT1(); }
        else                  { CP_WAIT0(); }
        __syncthreads();

        const uint32_t kST = sK + (uint32_t)s * KV_STAGE;
        const uint32_t vST = sV + (uint32_t)s * KV_STAGE;

        // scores = bias + mask, then += Q K^T
        float sc[8][4];
        #pragma unroll
        for (int nt = 0; nt < 8; nt++) {
            const int cs = nt * 8 + 2 * tig;
            const float ma = madd[s][cs], mb = madd[s][cs + 1];
            float2 blo = *(const float2*)(Bp0 + (size_t)gid       * S_ + s0 + cs);
            float2 bhi = *(const float2*)(Bp0 + (size_t)(gid + 8) * S_ + s0 + cs);
            sc[nt][0] = blo.x + ma; sc[nt][1] = blo.y + mb;
            sc[nt][2] = bhi.x + ma; sc[nt][3] = bhi.y + mb;
        }
        #pragma unroll
        for (int ks = 0; ks < 4; ks++) {
            #pragma unroll
            for (int ntp = 0; ntp < 4; ntp++) {
                uint32_t r0, r1, r2, r3;
                const uint32_t addr = kST + (ntp * 16 + rB) * 128
                                    + (((2 * ks + cB) ^ x_) << 4);
                LDSM4(r0, r1, r2, r3, addr);
                mma16(sc[2*ntp],   qa[ks], r0, r1);
                mma16(sc[2*ntp+1], qa[ks], r2, r3);
            }
        }

        // online softmax
        float rm0 = -1e30f, rm1 = -1e30f;
        #pragma unroll
        for (int nt = 0; nt < 8; nt++) {
            rm0 = fmaxf(rm0, fmaxf(sc[nt][0], sc[nt][1]));
            rm1 = fmaxf(rm1, fmaxf(sc[nt][2], sc[nt][3]));
        }
        rm0 = fmaxf(rm0, __shfl_xor_sync(0xffffffffu, rm0, 1));
        rm0 = fmaxf(rm0, __shfl_xor_sync(0xffffffffu, rm0, 2));
        rm1 = fmaxf(rm1, __shfl_xor_sync(0xffffffffu, rm1, 1));
        rm1 = fmaxf(rm1, __shfl_xor_sync(0xffffffffu, rm1, 2));
        const float mn0 = fmaxf(mr0, rm0), mn1 = fmaxf(mr1, rm1);
        const float c0 = __expf(mr0 - mn0), c1 = __expf(mr1 - mn1);
        mr0 = mn0; mr1 = mn1;

        uint32_t ph[8][2];
        float ps0 = 0.0f, ps1 = 0.0f;
        #pragma unroll
        for (int nt = 0; nt < 8; nt++) {
            const float p00 = __expf(sc[nt][0] - mn0);
            const float p01 = __expf(sc[nt][1] - mn0);
            const float p10 = __expf(sc[nt][2] - mn1);
            const float p11 = __expf(sc[nt][3] - mn1);
            ps0 += p00 + p01; ps1 += p10 + p11;
            ph[nt][0] = h2(p00, p01);
            ph[nt][1] = h2(p10, p11);
        }
        ps0 += __shfl_xor_sync(0xffffffffu, ps0, 1);
        ps0 += __shfl_xor_sync(0xffffffffu, ps0, 2);
        ps1 += __shfl_xor_sync(0xffffffffu, ps1, 1);
        ps1 += __shfl_xor_sync(0xffffffffu, ps1, 2);
        l0 = l0 * c0 + ps0;
        l1 = l1 * c1 + ps1;
        #pragma unroll
        for (int nt = 0; nt < 8; nt++) {
            oa[nt][0] *= c0; oa[nt][1] *= c0;
            oa[nt][2] *= c1; oa[nt][3] *= c1;
        }

        // O += P V  (V frags via ldmatrix.trans)
        #pragma unroll
        for (int ks2 = 0; ks2 < 4; ks2++) {
            uint32_t pf[4];
            pf[0] = ph[2*ks2][0];   pf[1] = ph[2*ks2][1];
            pf[2] = ph[2*ks2+1][0]; pf[3] = ph[2*ks2+1][1];
            #pragma unroll
            for (int ntp = 0; ntp < 4; ntp++) {
                uint32_t r0, r1, r2, r3;
                const uint32_t addr = vST + (ks2 * 16 + rA) * 128
                                    + (((ntp * 2 + cA) ^ x_) << 4);
                LDSM4T(r0, r1, r2, r3, addr);
                mma16(oa[2*ntp],   pf, r0, r1);
                mma16(oa[2*ntp+1], pf, r2, r3);
            }
        }
        __syncthreads();
    }

    // normalize + write context [B,T,D] fp16
    const float i0 = 1.0f / l0, i1 = 1.0f / l1;
    __half* Cb = Ctx + ((size_t)b * T_ + t0 + tw) * D_ + h * HD_;
    #pragma unroll
    for (int nt = 0; nt < 8; nt++) {
        *(uint32_t*)(Cb + (size_t)gid       * D_ + nt * 8 + 2 * tig)
            = h2(oa[nt][0] * i0, oa[nt][1] * i0);
        *(uint32_t*)(Cb + (size_t)(gid + 8) * D_ + nt * 8 + 2 * tig)
            = h2(oa[nt][2] * i1, oa[nt][3] * i1);
    }
}

// ---------------------------------------------------------------------------
extern "C" void kernel_launch(void* const* d_in, const int* in_sizes, int n_in,
                              void* d_out, int out_size)
{
    (void)in_sizes; (void)n_in; (void)out_size;
    const float* query = (const float*)d_in[0];
    const float* key   = (const float*)d_in[1];
    const float* value = (const float*)d_in[2];
    const float* bias  = (const float*)d_in[3];
    const unsigned char* mask = (const unsigned char*)d_in[4];
    const float* Wq = (const float*)d_in[5];
    const float* bq = (const float*)d_in[6];
    const float* Wk = (const float*)d_in[7];
    const float* bk = (const float*)d_in[8];
    const float* Wv = (const float*)d_in[9];
    const float* bv = (const float*)d_in[10];
    const float* Wo = (const float*)d_in[11];
    const float* bo = (const float*)d_in[12];

    __half *qh, *kh, *vh, *wqh, *wkh, *wvh, *woh, *qp, *kp, *vp, *ch;
    cudaGetSymbolAddress((void**)&qh,  g_qh);
    cudaGetSymbolAddress((void**)&kh,  g_kh);
    cudaGetSymbolAddress((void**)&vh,  g_vh);
    cudaGetSymbolAddress((void**)&wqh, g_Wqh);
    cudaGetSymbolAddress((void**)&wkh, g_Wkh);
    cudaGetSymbolAddress((void**)&wvh, g_Wvh);
    cudaGetSymbolAddress((void**)&woh, g_Woh);
    cudaGetSymbolAddress((void**)&qp,  g_Q);
    cudaGetSymbolAddress((void**)&kp,  g_K);
    cudaGetSymbolAddress((void**)&vp,  g_V);
    cudaGetSymbolAddress((void**)&ch,  g_Ch);

    cudaFuncSetAttribute(gemm_h, cudaFuncAttributeMaxDynamicSharedMemorySize,
                         G_SMEM);

    // fp32 -> fp16 conversions
    const int nIn4 = B_ * T_ * D_ / 4;   // 1048576
    const int nW4  = D_ * D_ / 4;        // 262144
    cvt_h<<<nIn4 / 256, 256>>>((const float4*)query, (uint2*)qh, nIn4);
    cvt_h<<<nIn4 / 256, 256>>>((const float4*)key,   (uint2*)kh, nIn4);
    cvt_h<<<nIn4 / 256, 256>>>((const float4*)value, (uint2*)vh, nIn4);
    cvt_h<<<nW4 / 256, 256>>>((const float4*)Wq, (uint2*)wqh, nW4);
    cvt_h<<<nW4 / 256, 256>>>((const float4*)Wk, (uint2*)wkh, nW4);
    cvt_h<<<nW4 / 256, 256>>>((const float4*)Wv, (uint2*)wvh, nW4);
    cvt_h<<<nW4 / 256, 256>>>((const float4*)Wo, (uint2*)woh, nW4);

    const dim3 gemmGrid(D_ / 128, (B_ * T_) / 128);  // (8, 32)
    const float qscale = 0.125f;  // 1/sqrt(HD), folded into Q projection

    gemm_h<<<gemmGrid, 256, G_SMEM>>>(qh, wqh, bq, qp, 1, qscale);
    gemm_h<<<gemmGrid, 256, G_SMEM>>>(kh, wkh, bk, kp, 1, 1.0f);
    gemm_h<<<gemmGrid, 256, G_SMEM>>>(vh, wvh, bv, vp, 1, 1.0f);

    attn_tc<<<dim3(T_ / 128, H_, B_), 256>>>(qp, kp, vp, bias, mask, ch);

    gemm_h<<<gemmGrid, 256, G_SMEM>>>(ch, woh, bo, (float*)d_out, 0, 1.0f);
}